// round 2
// baseline (speedup 1.0000x reference)
#include <cuda_runtime.h>
#include <math.h>

// ---------------- problem constants ----------------
#define BS    64
#define NSEG  3
#define SLEN  256
#define B3    192          // BS*NSEG
#define TT    768          // NSEG*SLEN
#define EDIM  300
#define HDIM  512
#define G3    1536         // 3*HDIM
#define NNODE 18
#define NFEAT 600
#define NHID  600
#define NOUT  1024
#define BN    1152         // BS*NNODE

// output layout (floats)
#define OUT_RFTS 0UL
#define OUT_EMBS 25165824UL                  // 64*768*512
#define OUT_MSKS 39911424UL                  // + 64*768*300
#define OUT_SG   39960576UL                  // + 64*768
#define OUT_HIDS 41140224UL                  // + 64*18*1024

// ---------------- scratch ----------------
__device__ float g_xi[(size_t)B3 * SLEN * G3];     // 302 MB
__device__ float g_h[2][B3 * HDIM];
__device__ float g_wihT[EDIM * G3];                // [e][g]
__device__ float g_whhP[G3 * HDIM];                // packed [gate][e4][k][4]
__device__ float g_t1[BN * NHID];
__device__ float g_h1[BN * NHID];
__device__ float g_t2[BN * NOUT];
__device__ int   g_len[B3];
__device__ int   g_off[B3];
__device__ int   g_tlen[BS];

// ---------------- prep ----------------
__global__ void prep_kernel(const int* __restrict__ lens) {
    int b3 = threadIdx.x;
    if (b3 < B3) {
        int bb = b3 / NSEG, s = b3 % NSEG;
        g_len[b3] = lens[b3];
        int off = 0;
        for (int s2 = 0; s2 < s; s2++) off += lens[bb * NSEG + s2];
        g_off[b3] = off;
        if (s == 0)
            g_tlen[bb] = lens[bb*NSEG] + lens[bb*NSEG+1] + lens[bb*NSEG+2];
    }
}

__global__ void zero_h_kernel() {
    int i = blockIdx.x * blockDim.x + threadIdx.x;
    if (i < B3 * HDIM) g_h[0][i] = 0.f;
}

// ---------------- weight reshapes ----------------
__global__ void transpose_wih_kernel(const float* __restrict__ w_ih) {
    // g_wihT[e*1536 + g] = w_ih[g*300 + e]
    for (int idx = blockIdx.x * blockDim.x + threadIdx.x;
         idx < EDIM * G3; idx += gridDim.x * blockDim.x) {
        int e = idx / G3, g = idx % G3;
        g_wihT[idx] = w_ih[g * EDIM + e];
    }
}

__global__ void pack_whh_kernel(const float* __restrict__ w_hh) {
    // dst[((g*128 + e4)*512 + k)*4 + c] = w_hh[(g*512 + k)*512 + e4*4 + c]
    for (int o = blockIdx.x * blockDim.x + threadIdx.x;
         o < G3 * HDIM; o += gridDim.x * blockDim.x) {
        int c  = o & 3;
        int k  = (o >> 2) & 511;
        int e4 = (o >> 11) & 127;
        int g  = o >> 18;
        g_whhP[o] = w_hh[((g * 512 + k) * 512) + e4 * 4 + c];
    }
}

// ---------------- xi = gather(emb) @ w_ih^T + b_ih  (masked tiles skipped) ----------------
__global__ __launch_bounds__(256)
void xi_gemm_kernel(const int* __restrict__ inds, const float* __restrict__ emb,
                    const float* __restrict__ b_ih) {
    const int BK = 20;
    int tr = blockIdx.y * 64;      // row tile (rows = b3*256 + t)
    int n0 = blockIdx.x * 64;      // col tile in [0,1536)
    int b3 = tr >> 8;
    int t0 = tr & 255;
    if (t0 >= g_len[b3]) return;   // fully-invalid tile: skip

    __shared__ float As[BK * 64];
    __shared__ float Bs[BK * 64];
    __shared__ int   toksh[64];

    int tid = threadIdx.x;
    int tx = tid & 15, ty = tid >> 4;
    if (tid < 64) toksh[tid] = inds[tr + tid];
    __syncthreads();

    float acc[4][4];
#pragma unroll
    for (int i = 0; i < 4; i++)
#pragma unroll
        for (int j = 0; j < 4; j++) acc[i][j] = 0.f;

    for (int kc = 0; kc < 15; kc++) {
        int e0 = kc * BK;
#pragma unroll
        for (int i = 0; i < 5; i++) {
            int idx = tid + i * 256;          // 1280 elems
            int r = idx / BK, e = idx % BK;
            As[e * 64 + r] = emb[(size_t)toksh[r] * EDIM + e0 + e];
        }
#pragma unroll
        for (int i = 0; i < 5; i++) {
            int idx = tid + i * 256;
            int e = idx >> 6, n = idx & 63;
            Bs[e * 64 + n] = g_wihT[(size_t)(e0 + e) * G3 + n0 + n];
        }
        __syncthreads();
#pragma unroll
        for (int e = 0; e < BK; e++) {
            float4 a = *(const float4*)&As[e * 64 + ty * 4];
            float4 b = *(const float4*)&Bs[e * 64 + tx * 4];
            acc[0][0] = fmaf(a.x, b.x, acc[0][0]); acc[0][1] = fmaf(a.x, b.y, acc[0][1]);
            acc[0][2] = fmaf(a.x, b.z, acc[0][2]); acc[0][3] = fmaf(a.x, b.w, acc[0][3]);
            acc[1][0] = fmaf(a.y, b.x, acc[1][0]); acc[1][1] = fmaf(a.y, b.y, acc[1][1]);
            acc[1][2] = fmaf(a.y, b.z, acc[1][2]); acc[1][3] = fmaf(a.y, b.w, acc[1][3]);
            acc[2][0] = fmaf(a.z, b.x, acc[2][0]); acc[2][1] = fmaf(a.z, b.y, acc[2][1]);
            acc[2][2] = fmaf(a.z, b.z, acc[2][2]); acc[2][3] = fmaf(a.z, b.w, acc[2][3]);
            acc[3][0] = fmaf(a.w, b.x, acc[3][0]); acc[3][1] = fmaf(a.w, b.y, acc[3][1]);
            acc[3][2] = fmaf(a.w, b.z, acc[3][2]); acc[3][3] = fmaf(a.w, b.w, acc[3][3]);
        }
        __syncthreads();
    }
#pragma unroll
    for (int i = 0; i < 4; i++) {
        int rg = tr + ty * 4 + i;
#pragma unroll
        for (int j = 0; j < 4; j++) {
            int cg = n0 + tx * 4 + j;
            g_xi[(size_t)rg * G3 + cg] = acc[i][j] + b_ih[cg];
        }
    }
}

// ---------------- GRU step (one kernel per timestep, graph-captured) ----------------
__device__ __forceinline__ float sigmoidf_(float x) { return 1.f / (1.f + expf(-x)); }

__global__ __launch_bounds__(512, 2)
void gru_step_kernel(int t, int cur, int nxt,
                     const float* __restrict__ b_hh, float* __restrict__ out) {
    __shared__ float hsh[16 * HDIM];          // 32 KB: h for this CTA's 16 batch rows
    int bt = blockIdx.y, kt = blockIdx.x;
    int tid = threadIdx.x;

    // stage h_cur for 16 b's
    const float* hc = g_h[cur] + (size_t)(bt * 16) * HDIM;
    for (int i = tid; i < 16 * HDIM; i += 512) hsh[i] = hc[i];
    __syncthreads();

    int w = tid >> 5, lane = tid & 31;
    int b = bt * 16 + w;
    int k = kt * 32 + lane;
    int lenb = g_len[b];
    float hold = hsh[(w << 9) + k];
    float hnew;

    if (t < lenb) {
        const float4* Wp  = (const float4*)g_whhP;
        const float4* hv4 = (const float4*)(hsh + (w << 9));
        float ar = 0.f, az = 0.f, an = 0.f;
#pragma unroll 2
        for (int e4 = 0; e4 < 128; e4++) {
            float4 h4 = hv4[e4];
            float4 w0 = Wp[(size_t)(0 * 128 + e4) * 512 + k];
            float4 w1 = Wp[(size_t)(1 * 128 + e4) * 512 + k];
            float4 w2 = Wp[(size_t)(2 * 128 + e4) * 512 + k];
            ar = fmaf(w0.x, h4.x, ar); ar = fmaf(w0.y, h4.y, ar);
            ar = fmaf(w0.z, h4.z, ar); ar = fmaf(w0.w, h4.w, ar);
            az = fmaf(w1.x, h4.x, az); az = fmaf(w1.y, h4.y, az);
            az = fmaf(w1.z, h4.z, az); az = fmaf(w1.w, h4.w, az);
            an = fmaf(w2.x, h4.x, an); an = fmaf(w2.y, h4.y, an);
            an = fmaf(w2.z, h4.z, an); an = fmaf(w2.w, h4.w, an);
        }
        ar += b_hh[k]; az += b_hh[512 + k]; an += b_hh[1024 + k];
        const float* xi = g_xi + (size_t)(b * 256 + t) * G3;
        float r = sigmoidf_(xi[k] + ar);
        float z = sigmoidf_(xi[512 + k] + az);
        float n = tanhf(xi[1024 + k] + r * an);
        hnew = (1.f - z) * n + z * hold;
        // packed ys write
        int pos = g_off[b] + t;
        int bb = b / 3;
        out[OUT_RFTS + ((size_t)bb * TT + pos) * HDIM + k] = hnew;
    } else {
        hnew = hold;
    }
    g_h[nxt][(size_t)b * HDIM + k] = hnew;
}

__global__ void copy_hids_kernel(float* __restrict__ out) {
    int b3 = blockIdx.x;
    out[OUT_HIDS + (size_t)b3 * HDIM + threadIdx.x] = g_h[0][(size_t)b3 * HDIM + threadIdx.x];
}

// ---------------- packing & masks ----------------
__global__ void msks_kernel(float* __restrict__ out) {
    int b = blockIdx.x, t = threadIdx.x;
    out[OUT_MSKS + (size_t)b * TT + t] = (t < g_tlen[b]) ? 1.f : 0.f;
}

__global__ void pack_emb_kernel(const int* __restrict__ inds,
                                const float* __restrict__ emb,
                                float* __restrict__ out) {
    int t = blockIdx.x, b3 = blockIdx.y;
    if (t >= g_len[b3]) return;
    int tok = inds[b3 * SLEN + t];
    size_t row = (size_t)(b3 / 3) * TT + g_off[b3] + t;
    for (int e = threadIdx.x; e < EDIM; e += blockDim.x)
        out[OUT_EMBS + row * EDIM + e] = emb[(size_t)tok * EDIM + e];
}

// ---------------- generic small GEMM: C[M,N] = A[M,K] @ B[K,N] ----------------
__global__ __launch_bounds__(256)
void gemm64_kernel(const float* __restrict__ A, const float* __restrict__ B,
                   float* __restrict__ C, int M, int N, int K) {
    const int BK = 8;
    int m0 = blockIdx.y * 64, n0 = blockIdx.x * 64;
    __shared__ float As[BK * 64];
    __shared__ float Bs[BK * 64];
    int tid = threadIdx.x;
    int tx = tid & 15, ty = tid >> 4;

    float acc[4][4];
#pragma unroll
    for (int i = 0; i < 4; i++)
#pragma unroll
        for (int j = 0; j < 4; j++) acc[i][j] = 0.f;

    for (int k0 = 0; k0 < K; k0 += BK) {
#pragma unroll
        for (int i = 0; i < 2; i++) {
            int idx = tid + i * 256;            // 512 A elems
            int r = idx / BK, e = idx % BK;
            float v = 0.f;
            if (m0 + r < M) v = A[(size_t)(m0 + r) * K + k0 + e];
            As[e * 64 + r] = v;
        }
#pragma unroll
        for (int i = 0; i < 2; i++) {
            int idx = tid + i * 256;
            int e = idx >> 6, n = idx & 63;
            float v = 0.f;
            if (n0 + n < N) v = B[(size_t)(k0 + e) * N + n0 + n];
            Bs[e * 64 + n] = v;
        }
        __syncthreads();
#pragma unroll
        for (int e = 0; e < BK; e++) {
            float4 a = *(const float4*)&As[e * 64 + ty * 4];
            float4 b = *(const float4*)&Bs[e * 64 + tx * 4];
            acc[0][0] = fmaf(a.x, b.x, acc[0][0]); acc[0][1] = fmaf(a.x, b.y, acc[0][1]);
            acc[0][2] = fmaf(a.x, b.z, acc[0][2]); acc[0][3] = fmaf(a.x, b.w, acc[0][3]);
            acc[1][0] = fmaf(a.y, b.x, acc[1][0]); acc[1][1] = fmaf(a.y, b.y, acc[1][1]);
            acc[1][2] = fmaf(a.y, b.z, acc[1][2]); acc[1][3] = fmaf(a.y, b.w, acc[1][3]);
            acc[2][0] = fmaf(a.z, b.x, acc[2][0]); acc[2][1] = fmaf(a.z, b.y, acc[2][1]);
            acc[2][2] = fmaf(a.z, b.z, acc[2][2]); acc[2][3] = fmaf(a.z, b.w, acc[2][3]);
            acc[3][0] = fmaf(a.w, b.x, acc[3][0]); acc[3][1] = fmaf(a.w, b.y, acc[3][1]);
            acc[3][2] = fmaf(a.w, b.z, acc[3][2]); acc[3][3] = fmaf(a.w, b.w, acc[3][3]);
        }
        __syncthreads();
    }
#pragma unroll
    for (int i = 0; i < 4; i++) {
        int rg = m0 + ty * 4 + i;
        if (rg >= M) continue;
#pragma unroll
        for (int j = 0; j < 4; j++) {
            int cg = n0 + tx * 4 + j;
            if (cg < N) C[(size_t)rg * N + cg] = acc[i][j];
        }
    }
}

// Y[b,n,f] = (relu?)(bias[f] + sum_m adj[b,n,m] * X[b,m,f])
__global__ void adjmul_kernel(const float* __restrict__ adj, const float* __restrict__ X,
                              const float* __restrict__ bias, float* __restrict__ Y,
                              int F, int relu) {
    int total = BS * NNODE * F;
    for (int idx = blockIdx.x * blockDim.x + threadIdx.x; idx < total;
         idx += gridDim.x * blockDim.x) {
        int f = idx % F;
        int n = (idx / F) % NNODE;
        int b = idx / (F * NNODE);
        const float* Xb = X + (size_t)(b * NNODE) * F;
        const float* ad = adj + (size_t)(b * NNODE + n) * NNODE;
        float acc = bias[f];
#pragma unroll
        for (int m = 0; m < NNODE; m++)
            acc = fmaf(ad[m], Xb[(size_t)m * F + f], acc);
        if (relu) acc = fmaxf(acc, 0.f);
        Y[idx] = acc;
    }
}

// ---------------- host ----------------
extern "C" void kernel_launch(void* const* d_in, const int* in_sizes, int n_in,
                              void* d_out, int out_size) {
    const int*   inds = (const int*)  d_in[0];
    const int*   lens = (const int*)  d_in[1];
    const float* emb  = (const float*)d_in[2];
    const float* w_ih = (const float*)d_in[3];
    const float* w_hh = (const float*)d_in[4];
    const float* b_ih = (const float*)d_in[5];
    const float* b_hh = (const float*)d_in[6];
    const float* sg_x = (const float*)d_in[7];
    const float* adj  = (const float*)d_in[8];
    const float* gw1  = (const float*)d_in[9];
    const float* gb1  = (const float*)d_in[10];
    const float* gw2  = (const float*)d_in[11];
    const float* gb2  = (const float*)d_in[12];
    float* out = (float*)d_out;

    cudaMemsetAsync(d_out, 0, (size_t)out_size * sizeof(float), 0);
    zero_h_kernel<<<(B3 * HDIM + 511) / 512, 512>>>();
    prep_kernel<<<1, 256>>>(lens);
    transpose_wih_kernel<<<512, 256>>>(w_ih);
    pack_whh_kernel<<<768, 256>>>(w_hh);

    xi_gemm_kernel<<<dim3(G3 / 64, (B3 * SLEN) / 64), 256>>>(inds, emb, b_ih);

    msks_kernel<<<BS, TT>>>(out);
    pack_emb_kernel<<<dim3(SLEN, B3), 64>>>(inds, emb, out);

    for (int t = 0; t < SLEN; t++)
        gru_step_kernel<<<dim3(16, 12), 512>>>(t, t & 1, (t + 1) & 1, b_hh, out);

    copy_hids_kernel<<<B3, HDIM>>>(out);

    // GCN
    gemm64_kernel<<<dim3((NHID + 63) / 64, (BN + 63) / 64), 256>>>(sg_x, gw1, g_t1, BN, NHID, NFEAT);
    adjmul_kernel<<<1350, 512>>>(adj, g_t1, gb1, g_h1, NHID, 1);
    gemm64_kernel<<<dim3((NOUT + 63) / 64, (BN + 63) / 64), 256>>>(g_h1, gw2, g_t2, BN, NOUT, NHID);
    adjmul_kernel<<<2304, 512>>>(adj, g_t2, gb2, out + OUT_SG, NOUT, 0);
}

// round 3
// speedup vs baseline: 1.3322x; 1.3322x over previous
#include <cuda_runtime.h>
#include <math.h>

// ---------------- problem constants ----------------
#define BS    64
#define NSEG  3
#define SLEN  256
#define B3    192
#define TT    768
#define EDIM  300
#define HDIM  512
#define G3    1536
#define NNODE 18
#define NFEAT 600
#define NHID  600
#define NOUT  1024
#define BN    1152

// persistent GRU geometry
#define NKG   16          // k-groups (32 h-columns each)
#define NBG   9           // b-groups
#define GB    22          // batch rows per b-group (last group = 16)

// output layout (floats)
#define OUT_RFTS 0UL
#define OUT_EMBS 25165824UL
#define OUT_MSKS 39911424UL
#define OUT_SG   39960576UL
#define OUT_HIDS 41140224UL

// ---------------- scratch ----------------
__device__ float g_xi[(size_t)B3 * SLEN * G3];
__device__ float g_h[2][B3 * HDIM];
__device__ float g_wihT[EDIM * G3];
__device__ float g_t1[BN * NHID];
__device__ float g_h1[BN * NHID];
__device__ float g_t2[BN * NOUT];
__device__ int   g_len[B3];
__device__ int   g_off[B3];
__device__ int   g_tlen[BS];
__device__ int   g_gmax[NBG];
__device__ int   g_bar_cnt[NBG];
__device__ int   g_bar_gen[NBG];

// ---------------- prep ----------------
__global__ void prep_kernel(const int* __restrict__ lens) {
    int i = threadIdx.x;
    if (i < B3) {
        int bb = i / NSEG, s = i % NSEG;
        g_len[i] = lens[i];
        int off = 0;
        for (int s2 = 0; s2 < s; s2++) off += lens[bb * NSEG + s2];
        g_off[i] = off;
        if (s == 0)
            g_tlen[bb] = lens[bb*NSEG] + lens[bb*NSEG+1] + lens[bb*NSEG+2];
    }
    if (i < NBG) {
        g_bar_cnt[i] = 0;
        g_bar_gen[i] = 0;
        int b0 = i * GB, be = min(b0 + GB, B3), m = 0;
        for (int b = b0; b < be; b++) m = max(m, lens[b]);
        g_gmax[i] = m;
    }
}

__global__ void zero_h_kernel() {
    int i = blockIdx.x * blockDim.x + threadIdx.x;
    if (i < B3 * HDIM) g_h[0][i] = 0.f;
}

__global__ void transpose_wih_kernel(const float* __restrict__ w_ih) {
    for (int idx = blockIdx.x * blockDim.x + threadIdx.x;
         idx < EDIM * G3; idx += gridDim.x * blockDim.x) {
        int e = idx / G3, g = idx % G3;
        g_wihT[idx] = w_ih[g * EDIM + e];
    }
}

// ---------------- xi = gather(emb) @ w_ih^T + b_ih ----------------
__global__ __launch_bounds__(256)
void xi_gemm_kernel(const int* __restrict__ inds, const float* __restrict__ emb,
                    const float* __restrict__ b_ih) {
    const int BK = 20;
    int tr = blockIdx.y * 64;
    int n0 = blockIdx.x * 64;
    int b3 = tr >> 8;
    int t0 = tr & 255;
    if (t0 >= g_len[b3]) return;

    __shared__ float As[BK * 64];
    __shared__ float Bs[BK * 64];
    __shared__ int   toksh[64];

    int tid = threadIdx.x;
    int tx = tid & 15, ty = tid >> 4;
    if (tid < 64) toksh[tid] = inds[tr + tid];
    __syncthreads();

    float acc[4][4];
#pragma unroll
    for (int i = 0; i < 4; i++)
#pragma unroll
        for (int j = 0; j < 4; j++) acc[i][j] = 0.f;

    for (int kc = 0; kc < 15; kc++) {
        int e0 = kc * BK;
#pragma unroll
        for (int i = 0; i < 5; i++) {
            int idx = tid + i * 256;
            int r = idx / BK, e = idx % BK;
            As[e * 64 + r] = emb[(size_t)toksh[r] * EDIM + e0 + e];
        }
#pragma unroll
        for (int i = 0; i < 5; i++) {
            int idx = tid + i * 256;
            int e = idx >> 6, n = idx & 63;
            Bs[e * 64 + n] = g_wihT[(size_t)(e0 + e) * G3 + n0 + n];
        }
        __syncthreads();
#pragma unroll
        for (int e = 0; e < BK; e++) {
            float4 a = *(const float4*)&As[e * 64 + ty * 4];
            float4 b = *(const float4*)&Bs[e * 64 + tx * 4];
            acc[0][0] = fmaf(a.x, b.x, acc[0][0]); acc[0][1] = fmaf(a.x, b.y, acc[0][1]);
            acc[0][2] = fmaf(a.x, b.z, acc[0][2]); acc[0][3] = fmaf(a.x, b.w, acc[0][3]);
            acc[1][0] = fmaf(a.y, b.x, acc[1][0]); acc[1][1] = fmaf(a.y, b.y, acc[1][1]);
            acc[1][2] = fmaf(a.y, b.z, acc[1][2]); acc[1][3] = fmaf(a.y, b.w, acc[1][3]);
            acc[2][0] = fmaf(a.z, b.x, acc[2][0]); acc[2][1] = fmaf(a.z, b.y, acc[2][1]);
            acc[2][2] = fmaf(a.z, b.z, acc[2][2]); acc[2][3] = fmaf(a.z, b.w, acc[2][3]);
            acc[3][0] = fmaf(a.w, b.x, acc[3][0]); acc[3][1] = fmaf(a.w, b.y, acc[3][1]);
            acc[3][2] = fmaf(a.w, b.z, acc[3][2]); acc[3][3] = fmaf(a.w, b.w, acc[3][3]);
        }
        __syncthreads();
    }
#pragma unroll
    for (int i = 0; i < 4; i++) {
        int rg = tr + ty * 4 + i;
#pragma unroll
        for (int j = 0; j < 4; j++) {
            int cg = n0 + tx * 4 + j;
            g_xi[(size_t)rg * G3 + cg] = acc[i][j] + b_ih[cg];
        }
    }
}

// ---------------- persistent GRU ----------------
#define SHFL4(d, s, src)                              \
    d.x = __shfl_sync(0xffffffffu, (s).x, (src));     \
    d.y = __shfl_sync(0xffffffffu, (s).y, (src));     \
    d.z = __shfl_sync(0xffffffffu, (s).z, (src));     \
    d.w = __shfl_sync(0xffffffffu, (s).w, (src));

#define FMA4(acc, wv, hv)                             \
    (acc).x = fmaf((wv).x, (hv).x, (acc).x);          \
    (acc).y = fmaf((wv).y, (hv).y, (acc).y);          \
    (acc).z = fmaf((wv).z, (hv).z, (acc).z);          \
    (acc).w = fmaf((wv).w, (hv).w, (acc).w);

__device__ __forceinline__ float sum4(float4 v) { return (v.x + v.y) + (v.z + v.w); }

__global__ __launch_bounds__(256, 1)
void gru_persist_kernel(const float* __restrict__ w_hh, const float* __restrict__ b_hh,
                        float* __restrict__ out) {
    extern __shared__ float4 W4[];   // [(j*3+gate)*32 + lane], j = e/4 block
    const int kg = blockIdx.x, bg = blockIdx.y;
    const int tid = threadIdx.x, lane = tid & 31, w = tid >> 5;

    // stage weight slice: W4[(j*3+g)*32+lc] = w_hh[(g*512 + kg*32+lc)*512 + 4j .. 4j+3]
    for (int i = tid; i < 128 * 3 * 32; i += 256) {
        int lc = i & 31, gj = i >> 5;
        int g = gj % 3, j = gj / 3;
        W4[i] = *(const float4*)&w_hh[(size_t)(g * HDIM + kg * 32 + lc) * HDIM + 4 * j];
    }

    const int k = kg * 32 + lane;
    const float bh_r = b_hh[k], bh_z = b_hh[HDIM + k], bh_n = b_hh[2 * HDIM + k];
    __syncthreads();

    const int gmax = g_gmax[bg];
    const int b0 = bg * GB;
    const int bend = min(b0 + GB, B3);
    const int bA = b0 + w * 3;

    int len_[3], row_[3];
#pragma unroll
    for (int j = 0; j < 3; j++) {
        int b = bA + j;
        bool v = b < bend;
        len_[j] = v ? g_len[b] : 0;
        row_[j] = v ? (b / NSEG) * TT + g_off[b] : 0;
    }

    for (int t = 0; t < gmax; t++) {
        const float* __restrict__ hc = g_h[t & 1];
        float* __restrict__ hn = g_h[(t + 1) & 1];
        const bool a0 = t < len_[0], a1 = t < len_[1], a2 = t < len_[2];
        const int nact = (int)a0 + (int)a1 + (int)a2;

        float AR[3], AZ[3], AN[3];
        AR[0]=AR[1]=AR[2]=0.f; AZ[0]=AZ[1]=AZ[2]=0.f; AN[0]=AN[1]=AN[2]=0.f;

        if (nact == 3) {
            // fused 3-b pass: weight LDS amortized over 3 batches
            const float4* h0p = (const float4*)(hc + (size_t)(bA + 0) * HDIM);
            const float4* h1p = (const float4*)(hc + (size_t)(bA + 1) * HDIM);
            const float4* h2p = (const float4*)(hc + (size_t)(bA + 2) * HDIM);
            float4 H0[4], H1[4], H2[4];
#pragma unroll
            for (int r = 0; r < 4; r++) {
                H0[r] = h0p[r * 32 + lane];
                H1[r] = h1p[r * 32 + lane];
                H2[r] = h2p[r * 32 + lane];
            }
            float4 z4 = make_float4(0.f, 0.f, 0.f, 0.f);
            float4 c0r=z4,c0z=z4,c0n=z4, c1r=z4,c1z=z4,c1n=z4, c2r=z4,c2z=z4,c2n=z4;
#pragma unroll
            for (int r = 0; r < 4; r++) {
                const float4* Wr = W4 + r * 3072;
#pragma unroll 4
                for (int s = 0; s < 32; s++) {
                    float4 w0 = Wr[s * 96 + lane];
                    float4 w1 = Wr[s * 96 + 32 + lane];
                    float4 w2 = Wr[s * 96 + 64 + lane];
                    float4 hb;
                    SHFL4(hb, H0[r], s);
                    FMA4(c0r, w0, hb); FMA4(c0z, w1, hb); FMA4(c0n, w2, hb);
                    SHFL4(hb, H1[r], s);
                    FMA4(c1r, w0, hb); FMA4(c1z, w1, hb); FMA4(c1n, w2, hb);
                    SHFL4(hb, H2[r], s);
                    FMA4(c2r, w0, hb); FMA4(c2z, w1, hb); FMA4(c2n, w2, hb);
                }
            }
            AR[0]=sum4(c0r); AZ[0]=sum4(c0z); AN[0]=sum4(c0n);
            AR[1]=sum4(c1r); AZ[1]=sum4(c1z); AN[1]=sum4(c1n);
            AR[2]=sum4(c2r); AZ[2]=sum4(c2z); AN[2]=sum4(c2n);
        } else if (nact > 0) {
#pragma unroll
            for (int j = 0; j < 3; j++) {
                bool aj = (j == 0) ? a0 : ((j == 1) ? a1 : a2);
                if (!aj) continue;
                const float4* hp = (const float4*)(hc + (size_t)(bA + j) * HDIM);
                float4 Hr[4];
#pragma unroll
                for (int r = 0; r < 4; r++) Hr[r] = hp[r * 32 + lane];
                float4 z4 = make_float4(0.f, 0.f, 0.f, 0.f);
                float4 cr = z4, cz = z4, cn = z4;
#pragma unroll
                for (int r = 0; r < 4; r++) {
                    const float4* Wr = W4 + r * 3072;
#pragma unroll 4
                    for (int s = 0; s < 32; s++) {
                        float4 hb;
                        SHFL4(hb, Hr[r], s);
                        float4 w0 = Wr[s * 96 + lane];
                        float4 w1 = Wr[s * 96 + 32 + lane];
                        float4 w2 = Wr[s * 96 + 64 + lane];
                        FMA4(cr, w0, hb); FMA4(cz, w1, hb); FMA4(cn, w2, hb);
                    }
                }
                AR[j] = sum4(cr); AZ[j] = sum4(cz); AN[j] = sum4(cn);
            }
        }

        // epilogue: gates + stores (active), carry (inactive)
#pragma unroll
        for (int j = 0; j < 3; j++) {
            int b = bA + j;
            if (b >= bend) break;
            float hold = hc[(size_t)b * HDIM + k];
            bool aj = t < len_[j];
            float hv = hold;
            if (aj) {
                const float* xi = g_xi + ((size_t)b * SLEN + t) * G3;
                float rr = 1.f / (1.f + expf(-(xi[k] + AR[j] + bh_r)));
                float zz = 1.f / (1.f + expf(-(xi[HDIM + k] + AZ[j] + bh_z)));
                float nn = tanhf(xi[2 * HDIM + k] + rr * (AN[j] + bh_n));
                hv = (1.f - zz) * nn + zz * hold;
                out[OUT_RFTS + ((size_t)(row_[j] + t)) * HDIM + k] = hv;
            }
            hn[(size_t)b * HDIM + k] = hv;
        }

        // per-b-group barrier among its NKG CTAs (sense via generation counter)
        __threadfence();
        __syncthreads();
        if (tid == 0) {
            int a = atomicAdd(&g_bar_cnt[bg], 1);
            if (a == NKG - 1) {
                atomicExch(&g_bar_cnt[bg], 0);
                __threadfence();
                atomicExch(&g_bar_gen[bg], t + 1);
            } else {
                while (atomicAdd(&g_bar_gen[bg], 0) <= t) { }
                __threadfence();
            }
        }
        __syncthreads();
    }

    // final hidden states (own slice only — no cross-CTA reads)
    const float* hf = g_h[gmax & 1];
#pragma unroll
    for (int j = 0; j < 3; j++) {
        int b = bA + j;
        if (b < bend)
            out[OUT_HIDS + (size_t)b * HDIM + k] = hf[(size_t)b * HDIM + k];
    }
}

// ---------------- packing & masks ----------------
__global__ void msks_kernel(float* __restrict__ out) {
    int b = blockIdx.x, t = threadIdx.x;
    out[OUT_MSKS + (size_t)b * TT + t] = (t < g_tlen[b]) ? 1.f : 0.f;
}

__global__ void pack_emb_kernel(const int* __restrict__ inds,
                                const float* __restrict__ emb,
                                float* __restrict__ out) {
    int t = blockIdx.x, b3 = blockIdx.y;
    if (t >= g_len[b3]) return;
    int tok = inds[b3 * SLEN + t];
    size_t row = (size_t)(b3 / 3) * TT + g_off[b3] + t;
    for (int e = threadIdx.x; e < EDIM; e += blockDim.x)
        out[OUT_EMBS + row * EDIM + e] = emb[(size_t)tok * EDIM + e];
}

// ---------------- generic small GEMM ----------------
__global__ __launch_bounds__(256)
void gemm64_kernel(const float* __restrict__ A, const float* __restrict__ B,
                   float* __restrict__ C, int M, int N, int K) {
    const int BK = 8;
    int m0 = blockIdx.y * 64, n0 = blockIdx.x * 64;
    __shared__ float As[BK * 64];
    __shared__ float Bs[BK * 64];
    int tid = threadIdx.x;
    int tx = tid & 15, ty = tid >> 4;

    float acc[4][4];
#pragma unroll
    for (int i = 0; i < 4; i++)
#pragma unroll
        for (int j = 0; j < 4; j++) acc[i][j] = 0.f;

    for (int k0 = 0; k0 < K; k0 += BK) {
#pragma unroll
        for (int i = 0; i < 2; i++) {
            int idx = tid + i * 256;
            int r = idx / BK, e = idx % BK;
            float v = 0.f;
            if (m0 + r < M) v = A[(size_t)(m0 + r) * K + k0 + e];
            As[e * 64 + r] = v;
        }
#pragma unroll
        for (int i = 0; i < 2; i++) {
            int idx = tid + i * 256;
            int e = idx >> 6, n = idx & 63;
            float v = 0.f;
            if (n0 + n < N) v = B[(size_t)(k0 + e) * N + n0 + n];
            Bs[e * 64 + n] = v;
        }
        __syncthreads();
#pragma unroll
        for (int e = 0; e < BK; e++) {
            float4 a = *(const float4*)&As[e * 64 + ty * 4];
            float4 b = *(const float4*)&Bs[e * 64 + tx * 4];
            acc[0][0] = fmaf(a.x, b.x, acc[0][0]); acc[0][1] = fmaf(a.x, b.y, acc[0][1]);
            acc[0][2] = fmaf(a.x, b.z, acc[0][2]); acc[0][3] = fmaf(a.x, b.w, acc[0][3]);
            acc[1][0] = fmaf(a.y, b.x, acc[1][0]); acc[1][1] = fmaf(a.y, b.y, acc[1][1]);
            acc[1][2] = fmaf(a.y, b.z, acc[1][2]); acc[1][3] = fmaf(a.y, b.w, acc[1][3]);
            acc[2][0] = fmaf(a.z, b.x, acc[2][0]); acc[2][1] = fmaf(a.z, b.y, acc[2][1]);
            acc[2][2] = fmaf(a.z, b.z, acc[2][2]); acc[2][3] = fmaf(a.z, b.w, acc[2][3]);
            acc[3][0] = fmaf(a.w, b.x, acc[3][0]); acc[3][1] = fmaf(a.w, b.y, acc[3][1]);
            acc[3][2] = fmaf(a.w, b.z, acc[3][2]); acc[3][3] = fmaf(a.w, b.w, acc[3][3]);
        }
        __syncthreads();
    }
#pragma unroll
    for (int i = 0; i < 4; i++) {
        int rg = m0 + ty * 4 + i;
        if (rg >= M) continue;
#pragma unroll
        for (int j = 0; j < 4; j++) {
            int cg = n0 + tx * 4 + j;
            if (cg < N) C[(size_t)rg * N + cg] = acc[i][j];
        }
    }
}

__global__ void adjmul_kernel(const float* __restrict__ adj, const float* __restrict__ X,
                              const float* __restrict__ bias, float* __restrict__ Y,
                              int F, int relu) {
    int total = BS * NNODE * F;
    for (int idx = blockIdx.x * blockDim.x + threadIdx.x; idx < total;
         idx += gridDim.x * blockDim.x) {
        int f = idx % F;
        int n = (idx / F) % NNODE;
        int b = idx / (F * NNODE);
        const float* Xb = X + (size_t)(b * NNODE) * F;
        const float* ad = adj + (size_t)(b * NNODE + n) * NNODE;
        float acc = bias[f];
#pragma unroll
        for (int m = 0; m < NNODE; m++)
            acc = fmaf(ad[m], Xb[(size_t)m * F + f], acc);
        if (relu) acc = fmaxf(acc, 0.f);
        Y[idx] = acc;
    }
}

// ---------------- host ----------------
extern "C" void kernel_launch(void* const* d_in, const int* in_sizes, int n_in,
                              void* d_out, int out_size) {
    const int*   inds = (const int*)  d_in[0];
    const int*   lens = (const int*)  d_in[1];
    const float* emb  = (const float*)d_in[2];
    const float* w_ih = (const float*)d_in[3];
    const float* w_hh = (const float*)d_in[4];
    const float* b_ih = (const float*)d_in[5];
    const float* b_hh = (const float*)d_in[6];
    const float* sg_x = (const float*)d_in[7];
    const float* adj  = (const float*)d_in[8];
    const float* gw1  = (const float*)d_in[9];
    const float* gb1  = (const float*)d_in[10];
    const float* gw2  = (const float*)d_in[11];
    const float* gb2  = (const float*)d_in[12];
    float* out = (float*)d_out;

    const int WSMEM = 128 * 3 * 32 * 16;   // 196608 B dynamic smem
    cudaFuncSetAttribute(gru_persist_kernel,
                         cudaFuncAttributeMaxDynamicSharedMemorySize, WSMEM);

    cudaMemsetAsync(d_out, 0, (size_t)out_size * sizeof(float), 0);
    zero_h_kernel<<<(B3 * HDIM + 511) / 512, 512>>>();
    prep_kernel<<<1, 256>>>(lens);
    transpose_wih_kernel<<<512, 256>>>(w_ih);

    xi_gemm_kernel<<<dim3(G3 / 64, (B3 * SLEN) / 64), 256>>>(inds, emb, b_ih);

    msks_kernel<<<BS, TT>>>(out);
    pack_emb_kernel<<<dim3(SLEN, B3), 64>>>(inds, emb, out);

    gru_persist_kernel<<<dim3(NKG, NBG), 256, WSMEM>>>(w_hh, b_hh, out);

    // GCN
    gemm64_kernel<<<dim3((NHID + 63) / 64, (BN + 63) / 64), 256>>>(sg_x, gw1, g_t1, BN, NHID, NFEAT);
    adjmul_kernel<<<1350, 512>>>(adj, g_t1, gb1, g_h1, NHID, 1);
    gemm64_kernel<<<dim3((NOUT + 63) / 64, (BN + 63) / 64), 256>>>(g_h1, gw2, g_t2, BN, NOUT, NHID);
    adjmul_kernel<<<2304, 512>>>(adj, g_t2, gb2, out + OUT_SG, NOUT, 0);
}

// round 4
// speedup vs baseline: 1.6190x; 1.2152x over previous
#include <cuda_runtime.h>
#include <math.h>

// ---------------- problem constants ----------------
#define BS    64
#define NSEG  3
#define SLEN  256
#define B3    192
#define TT    768
#define EDIM  300
#define HDIM  512
#define G3    1536
#define NNODE 18
#define NFEAT 600
#define NHID  600
#define NOUT  1024
#define BN    1152

// persistent GRU geometry
#define NKG   16          // k-groups (32 h-columns each)
#define NBG   9           // b-groups
#define NSLOT 24          // 8 warps * 3 b-slots

// output layout (floats)
#define OUT_RFTS 0UL
#define OUT_EMBS 25165824UL
#define OUT_MSKS 39911424UL
#define OUT_SG   39960576UL
#define OUT_HIDS 41140224UL

// ---------------- scratch ----------------
__device__ float g_xi[(size_t)B3 * SLEN * G3];
__device__ float g_h[2][B3 * HDIM];
__device__ float g_wihT[EDIM * G3];
__device__ float g_t1[BN * NHID];
__device__ float g_h1[BN * NHID];
__device__ float g_t2[BN * NOUT];
__device__ int   g_len[B3];
__device__ int   g_off[B3];
__device__ int   g_tlen[BS];
__device__ int   g_gmax[NBG];
__device__ int   g_bar_cnt[NBG];
__device__ int   g_bar_gen[NBG];
__device__ int   g_bmap[NBG * NSLOT];

// ---------------- prep: lens/offsets + length-balanced group assignment ----------------
__global__ void prep_kernel(const int* __restrict__ lens) {
    __shared__ int s_len[B3];
    __shared__ int hist[257];
    __shared__ int sorted_b[B3];          // desc-by-len order
    int tid = threadIdx.x;

    for (int i = tid; i < 257; i += 256) hist[i] = 0;
    for (int i = tid; i < NBG * NSLOT; i += 256) g_bmap[i] = -1;
    if (tid < NBG) { g_bar_cnt[tid] = 0; g_bar_gen[tid] = 0; g_gmax[tid] = 0; }
    __syncthreads();

    if (tid < B3) {
        int l = lens[tid];
        s_len[tid] = l;
        g_len[tid] = l;
        atomicAdd(&hist[l], 1);
        int bb = tid / NSEG, s = tid % NSEG;
        int off = 0;
        for (int s2 = 0; s2 < s; s2++) off += lens[bb * NSEG + s2];
        g_off[tid] = off;
        if (s == 0)
            g_tlen[bb] = lens[bb*NSEG] + lens[bb*NSEG+1] + lens[bb*NSEG+2];
    }
    __syncthreads();
    if (tid == 0) {                        // exclusive prefix over bins 1..256
        int acc = 0;
        for (int v = 1; v <= 256; v++) { int c = hist[v]; hist[v] = acc; acc += c; }
    }
    __syncthreads();
    if (tid < B3) {
        int pos = atomicAdd(&hist[s_len[tid]], 1);   // ascending rank
        sorted_b[B3 - 1 - pos] = tid;                // descending order
    }
    __syncthreads();
    if (tid < B3) {
        int i = tid;                                 // desc rank
        int b = sorted_b[i];
        int p = i % (2 * NBG);
        int g = (p < NBG) ? p : (2 * NBG - 1 - p);   // snake deal
        int slot = 2 * (i / (2 * NBG)) + ((p >= NBG) ? 1 : 0);
        g_bmap[g * NSLOT + slot] = b;
        atomicMax(&g_gmax[g], s_len[b]);
    }
}

__global__ void zero_h_kernel() {
    int i = blockIdx.x * blockDim.x + threadIdx.x;
    if (i < B3 * HDIM) g_h[0][i] = 0.f;
}

__global__ void transpose_wih_kernel(const float* __restrict__ w_ih) {
    for (int idx = blockIdx.x * blockDim.x + threadIdx.x;
         idx < EDIM * G3; idx += gridDim.x * blockDim.x) {
        int e = idx / G3, g = idx % G3;
        g_wihT[idx] = w_ih[g * EDIM + e];
    }
}

// ---------------- xi = gather(emb) @ w_ih^T + b_ih : 128x64 tile, 8x4 microtile ----------------
#define XBM 128
#define XBN 64
#define XBK 16

__global__ __launch_bounds__(256, 2)
void xi_gemm_kernel(const int* __restrict__ inds, const float* __restrict__ emb,
                    const float* __restrict__ b_ih) {
    int tr = blockIdx.y * XBM;
    int n0 = blockIdx.x * XBN;
    int b3 = tr >> 8;
    int t0 = tr & 255;
    if (t0 >= g_len[b3]) return;

    __shared__ float As[XBK * XBM];      // [e][row]
    __shared__ float Bs[XBK * XBN];      // [e][n]
    __shared__ int   toksh[XBM];

    int tid = threadIdx.x;
    int tx = tid & 15, ty = tid >> 4;    // tx -> 4 cols, ty -> 8 rows
    if (tid < XBM) toksh[tid] = inds[tr + tid];
    __syncthreads();

    float acc[8][4];
#pragma unroll
    for (int i = 0; i < 8; i++)
#pragma unroll
        for (int j = 0; j < 4; j++) acc[i][j] = 0.f;

    const int rr = tid >> 2;             // 0..63 (A-load row base)
    const int e4 = (tid & 3) * 4;        // 0,4,8,12
    const int be = tid >> 4;             // 0..15 (B-load e)
    const int bn = (tid & 15) * 4;       // B-load col

    for (int e0 = 0; e0 < EDIM; e0 += XBK) {
        // A: 128 rows x 16 e, gathered; 2 float4 per thread, transposed store
#pragma unroll
        for (int i = 0; i < 2; i++) {
            int row = rr + i * 64;
            int e = e0 + e4;
            float4 v = make_float4(0.f, 0.f, 0.f, 0.f);
            const float* ep = emb + (size_t)toksh[row] * EDIM;
            if (e + 3 < EDIM) v = *(const float4*)(ep + e);
            else {
                if (e     < EDIM) v.x = ep[e];
                if (e + 1 < EDIM) v.y = ep[e + 1];
                if (e + 2 < EDIM) v.z = ep[e + 2];
                if (e + 3 < EDIM) v.w = ep[e + 3];
            }
            As[(e4 + 0) * XBM + row] = v.x;
            As[(e4 + 1) * XBM + row] = v.y;
            As[(e4 + 2) * XBM + row] = v.z;
            As[(e4 + 3) * XBM + row] = v.w;
        }
        // B: 16 e x 64 n, 1 float4 per thread
        {
            float4 v = make_float4(0.f, 0.f, 0.f, 0.f);
            if (e0 + be < EDIM)
                v = *(const float4*)&g_wihT[(size_t)(e0 + be) * G3 + n0 + bn];
            *(float4*)&Bs[be * XBN + bn] = v;
        }
        __syncthreads();
#pragma unroll
        for (int e = 0; e < XBK; e++) {
            float4 b = *(const float4*)&Bs[e * XBN + tx * 4];
            float4 a0 = *(const float4*)&As[e * XBM + ty * 8];
            float4 a1 = *(const float4*)&As[e * XBM + ty * 8 + 4];
            acc[0][0]=fmaf(a0.x,b.x,acc[0][0]); acc[0][1]=fmaf(a0.x,b.y,acc[0][1]); acc[0][2]=fmaf(a0.x,b.z,acc[0][2]); acc[0][3]=fmaf(a0.x,b.w,acc[0][3]);
            acc[1][0]=fmaf(a0.y,b.x,acc[1][0]); acc[1][1]=fmaf(a0.y,b.y,acc[1][1]); acc[1][2]=fmaf(a0.y,b.z,acc[1][2]); acc[1][3]=fmaf(a0.y,b.w,acc[1][3]);
            acc[2][0]=fmaf(a0.z,b.x,acc[2][0]); acc[2][1]=fmaf(a0.z,b.y,acc[2][1]); acc[2][2]=fmaf(a0.z,b.z,acc[2][2]); acc[2][3]=fmaf(a0.z,b.w,acc[2][3]);
            acc[3][0]=fmaf(a0.w,b.x,acc[3][0]); acc[3][1]=fmaf(a0.w,b.y,acc[3][1]); acc[3][2]=fmaf(a0.w,b.z,acc[3][2]); acc[3][3]=fmaf(a0.w,b.w,acc[3][3]);
            acc[4][0]=fmaf(a1.x,b.x,acc[4][0]); acc[4][1]=fmaf(a1.x,b.y,acc[4][1]); acc[4][2]=fmaf(a1.x,b.z,acc[4][2]); acc[4][3]=fmaf(a1.x,b.w,acc[4][3]);
            acc[5][0]=fmaf(a1.y,b.x,acc[5][0]); acc[5][1]=fmaf(a1.y,b.y,acc[5][1]); acc[5][2]=fmaf(a1.y,b.z,acc[5][2]); acc[5][3]=fmaf(a1.y,b.w,acc[5][3]);
            acc[6][0]=fmaf(a1.z,b.x,acc[6][0]); acc[6][1]=fmaf(a1.z,b.y,acc[6][1]); acc[6][2]=fmaf(a1.z,b.z,acc[6][2]); acc[6][3]=fmaf(a1.z,b.w,acc[6][3]);
            acc[7][0]=fmaf(a1.w,b.x,acc[7][0]); acc[7][1]=fmaf(a1.w,b.y,acc[7][1]); acc[7][2]=fmaf(a1.w,b.z,acc[7][2]); acc[7][3]=fmaf(a1.w,b.w,acc[7][3]);
        }
        __syncthreads();
    }
    float4 bias = *(const float4*)&b_ih[n0 + tx * 4];
#pragma unroll
    for (int i = 0; i < 8; i++) {
        int rg = tr + ty * 8 + i;
        float4 v = make_float4(acc[i][0] + bias.x, acc[i][1] + bias.y,
                               acc[i][2] + bias.z, acc[i][3] + bias.w);
        *(float4*)&g_xi[(size_t)rg * G3 + n0 + tx * 4] = v;
    }
}

// ---------------- persistent GRU ----------------
#define SHFL4(d, s, src)                              \
    d.x = __shfl_sync(0xffffffffu, (s).x, (src));     \
    d.y = __shfl_sync(0xffffffffu, (s).y, (src));     \
    d.z = __shfl_sync(0xffffffffu, (s).z, (src));     \
    d.w = __shfl_sync(0xffffffffu, (s).w, (src));

#define FMA4(acc, wv, hv)                             \
    (acc).x = fmaf((wv).x, (hv).x, (acc).x);          \
    (acc).y = fmaf((wv).y, (hv).y, (acc).y);          \
    (acc).z = fmaf((wv).z, (hv).z, (acc).z);          \
    (acc).w = fmaf((wv).w, (hv).w, (acc).w);

__device__ __forceinline__ float sum4(float4 v) { return (v.x + v.y) + (v.z + v.w); }

__global__ __launch_bounds__(256, 1)
void gru_persist_kernel(const float* __restrict__ w_hh, const float* __restrict__ b_hh,
                        float* __restrict__ out) {
    extern __shared__ float4 W4[];   // [(j*3+gate)*32 + lane], j = e/4 block
    const int kg = blockIdx.x, bg = blockIdx.y;
    const int tid = threadIdx.x, lane = tid & 31, w = tid >> 5;

    for (int i = tid; i < 128 * 3 * 32; i += 256) {
        int lc = i & 31, gj = i >> 5;
        int g = gj % 3, j = gj / 3;
        W4[i] = *(const float4*)&w_hh[(size_t)(g * HDIM + kg * 32 + lc) * HDIM + 4 * j];
    }

    const int k = kg * 32 + lane;
    const float bh_r = b_hh[k], bh_z = b_hh[HDIM + k], bh_n = b_hh[2 * HDIM + k];
    __syncthreads();

    const int gmax = g_gmax[bg];

    int bj[3], len_[3], row_[3];
#pragma unroll
    for (int j = 0; j < 3; j++) {
        int b = g_bmap[bg * NSLOT + w * 3 + j];
        bj[j] = b;
        len_[j] = (b >= 0) ? g_len[b] : 0;
        row_[j] = (b >= 0) ? (b / NSEG) * TT + g_off[b] : 0;
    }

    for (int t = 0; t < gmax; t++) {
        const float* __restrict__ hc = g_h[t & 1];
        float* __restrict__ hn = g_h[(t + 1) & 1];
        const bool a0 = t < len_[0], a1 = t < len_[1], a2 = t < len_[2];
        const int nact = (int)a0 + (int)a1 + (int)a2;

        float AR[3], AZ[3], AN[3];
        AR[0]=AR[1]=AR[2]=0.f; AZ[0]=AZ[1]=AZ[2]=0.f; AN[0]=AN[1]=AN[2]=0.f;

        if (nact == 3) {
            const float4* h0p = (const float4*)(hc + (size_t)bj[0] * HDIM);
            const float4* h1p = (const float4*)(hc + (size_t)bj[1] * HDIM);
            const float4* h2p = (const float4*)(hc + (size_t)bj[2] * HDIM);
            float4 H0[4], H1[4], H2[4];
#pragma unroll
            for (int r = 0; r < 4; r++) {
                H0[r] = h0p[r * 32 + lane];
                H1[r] = h1p[r * 32 + lane];
                H2[r] = h2p[r * 32 + lane];
            }
            float4 z4 = make_float4(0.f, 0.f, 0.f, 0.f);
            float4 c0r=z4,c0z=z4,c0n=z4, c1r=z4,c1z=z4,c1n=z4, c2r=z4,c2z=z4,c2n=z4;
#pragma unroll
            for (int r = 0; r < 4; r++) {
                const float4* Wr = W4 + r * 3072;
#pragma unroll 4
                for (int s = 0; s < 32; s++) {
                    float4 w0 = Wr[s * 96 + lane];
                    float4 w1 = Wr[s * 96 + 32 + lane];
                    float4 w2 = Wr[s * 96 + 64 + lane];
                    float4 hb;
                    SHFL4(hb, H0[r], s);
                    FMA4(c0r, w0, hb); FMA4(c0z, w1, hb); FMA4(c0n, w2, hb);
                    SHFL4(hb, H1[r], s);
                    FMA4(c1r, w0, hb); FMA4(c1z, w1, hb); FMA4(c1n, w2, hb);
                    SHFL4(hb, H2[r], s);
                    FMA4(c2r, w0, hb); FMA4(c2z, w1, hb); FMA4(c2n, w2, hb);
                }
            }
            AR[0]=sum4(c0r); AZ[0]=sum4(c0z); AN[0]=sum4(c0n);
            AR[1]=sum4(c1r); AZ[1]=sum4(c1z); AN[1]=sum4(c1n);
            AR[2]=sum4(c2r); AZ[2]=sum4(c2z); AN[2]=sum4(c2n);
        } else if (nact > 0) {
#pragma unroll
            for (int j = 0; j < 3; j++) {
                bool aj = (j == 0) ? a0 : ((j == 1) ? a1 : a2);
                if (!aj) continue;
                const float4* hp = (const float4*)(hc + (size_t)bj[j] * HDIM);
                float4 Hr[4];
#pragma unroll
                for (int r = 0; r < 4; r++) Hr[r] = hp[r * 32 + lane];
                float4 z4 = make_float4(0.f, 0.f, 0.f, 0.f);
                float4 cr = z4, cz = z4, cn = z4;
#pragma unroll
                for (int r = 0; r < 4; r++) {
                    const float4* Wr = W4 + r * 3072;
#pragma unroll 4
                    for (int s = 0; s < 32; s++) {
                        float4 hb;
                        SHFL4(hb, Hr[r], s);
                        float4 w0 = Wr[s * 96 + lane];
                        float4 w1 = Wr[s * 96 + 32 + lane];
                        float4 w2 = Wr[s * 96 + 64 + lane];
                        FMA4(cr, w0, hb); FMA4(cz, w1, hb); FMA4(cn, w2, hb);
                    }
                }
                AR[j] = sum4(cr); AZ[j] = sum4(cz); AN[j] = sum4(cn);
            }
        }

#pragma unroll
        for (int j = 0; j < 3; j++) {
            int b = bj[j];
            if (b < 0) continue;
            float hold = hc[(size_t)b * HDIM + k];
            float hv = hold;
            if (t < len_[j]) {
                const float* xi = g_xi + ((size_t)b * SLEN + t) * G3;
                float rr = 1.f / (1.f + expf(-(xi[k] + AR[j] + bh_r)));
                float zz = 1.f / (1.f + expf(-(xi[HDIM + k] + AZ[j] + bh_z)));
                float nn = tanhf(xi[2 * HDIM + k] + rr * (AN[j] + bh_n));
                hv = (1.f - zz) * nn + zz * hold;
                out[OUT_RFTS + ((size_t)(row_[j] + t)) * HDIM + k] = hv;
            }
            hn[(size_t)b * HDIM + k] = hv;
        }

        // per-b-group barrier among its NKG CTAs
        __threadfence();
        __syncthreads();
        if (tid == 0) {
            int a = atomicAdd(&g_bar_cnt[bg], 1);
            if (a == NKG - 1) {
                atomicExch(&g_bar_cnt[bg], 0);
                __threadfence();
                atomicExch(&g_bar_gen[bg], t + 1);
            } else {
                while (atomicAdd(&g_bar_gen[bg], 0) <= t) { }
                __threadfence();
            }
        }
        __syncthreads();
    }

    const float* hf = g_h[gmax & 1];
#pragma unroll
    for (int j = 0; j < 3; j++) {
        if (bj[j] >= 0)
            out[OUT_HIDS + (size_t)bj[j] * HDIM + k] = hf[(size_t)bj[j] * HDIM + k];
    }
}

// ---------------- packing & masks ----------------
__global__ void msks_kernel(float* __restrict__ out) {
    int b = blockIdx.x, t = threadIdx.x;
    out[OUT_MSKS + (size_t)b * TT + t] = (t < g_tlen[b]) ? 1.f : 0.f;
}

__global__ void pack_emb_kernel(const int* __restrict__ inds,
                                const float* __restrict__ emb,
                                float* __restrict__ out) {
    int t = blockIdx.x, b3 = blockIdx.y;
    if (t >= g_len[b3]) return;
    int tok = inds[b3 * SLEN + t];
    size_t row = (size_t)(b3 / 3) * TT + g_off[b3] + t;
    for (int e = threadIdx.x; e < EDIM; e += blockDim.x)
        out[OUT_EMBS + row * EDIM + e] = emb[(size_t)tok * EDIM + e];
}

// ---------------- generic small GEMM (GCN) ----------------
__global__ __launch_bounds__(256)
void gemm64_kernel(const float* __restrict__ A, const float* __restrict__ B,
                   float* __restrict__ C, int M, int N, int K) {
    const int BK = 8;
    int m0 = blockIdx.y * 64, n0 = blockIdx.x * 64;
    __shared__ float As[BK * 64];
    __shared__ float Bs[BK * 64];
    int tid = threadIdx.x;
    int tx = tid & 15, ty = tid >> 4;

    float acc[4][4];
#pragma unroll
    for (int i = 0; i < 4; i++)
#pragma unroll
        for (int j = 0; j < 4; j++) acc[i][j] = 0.f;

    for (int k0 = 0; k0 < K; k0 += BK) {
#pragma unroll
        for (int i = 0; i < 2; i++) {
            int idx = tid + i * 256;
            int r = idx / BK, e = idx % BK;
            float v = 0.f;
            if (m0 + r < M) v = A[(size_t)(m0 + r) * K + k0 + e];
            As[e * 64 + r] = v;
        }
#pragma unroll
        for (int i = 0; i < 2; i++) {
            int idx = tid + i * 256;
            int e = idx >> 6, n = idx & 63;
            float v = 0.f;
            if (n0 + n < N) v = B[(size_t)(k0 + e) * N + n0 + n];
            Bs[e * 64 + n] = v;
        }
        __syncthreads();
#pragma unroll
        for (int e = 0; e < BK; e++) {
            float4 a = *(const float4*)&As[e * 64 + ty * 4];
            float4 b = *(const float4*)&Bs[e * 64 + tx * 4];
            acc[0][0] = fmaf(a.x, b.x, acc[0][0]); acc[0][1] = fmaf(a.x, b.y, acc[0][1]);
            acc[0][2] = fmaf(a.x, b.z, acc[0][2]); acc[0][3] = fmaf(a.x, b.w, acc[0][3]);
            acc[1][0] = fmaf(a.y, b.x, acc[1][0]); acc[1][1] = fmaf(a.y, b.y, acc[1][1]);
            acc[1][2] = fmaf(a.y, b.z, acc[1][2]); acc[1][3] = fmaf(a.y, b.w, acc[1][3]);
            acc[2][0] = fmaf(a.z, b.x, acc[2][0]); acc[2][1] = fmaf(a.z, b.y, acc[2][1]);
            acc[2][2] = fmaf(a.z, b.z, acc[2][2]); acc[2][3] = fmaf(a.z, b.w, acc[2][3]);
            acc[3][0] = fmaf(a.w, b.x, acc[3][0]); acc[3][1] = fmaf(a.w, b.y, acc[3][1]);
            acc[3][2] = fmaf(a.w, b.z, acc[3][2]); acc[3][3] = fmaf(a.w, b.w, acc[3][3]);
        }
        __syncthreads();
    }
#pragma unroll
    for (int i = 0; i < 4; i++) {
        int rg = m0 + ty * 4 + i;
        if (rg >= M) continue;
#pragma unroll
        for (int j = 0; j < 4; j++) {
            int cg = n0 + tx * 4 + j;
            if (cg < N) C[(size_t)rg * N + cg] = acc[i][j];
        }
    }
}

__global__ void adjmul_kernel(const float* __restrict__ adj, const float* __restrict__ X,
                              const float* __restrict__ bias, float* __restrict__ Y,
                              int F, int relu) {
    int total = BS * NNODE * F;
    for (int idx = blockIdx.x * blockDim.x + threadIdx.x; idx < total;
         idx += gridDim.x * blockDim.x) {
        int f = idx % F;
        int n = (idx / F) % NNODE;
        int b = idx / (F * NNODE);
        const float* Xb = X + (size_t)(b * NNODE) * F;
        const float* ad = adj + (size_t)(b * NNODE + n) * NNODE;
        float acc = bias[f];
#pragma unroll
        for (int m = 0; m < NNODE; m++)
            acc = fmaf(ad[m], Xb[(size_t)m * F + f], acc);
        if (relu) acc = fmaxf(acc, 0.f);
        Y[idx] = acc;
    }
}

// ---------------- host ----------------
extern "C" void kernel_launch(void* const* d_in, const int* in_sizes, int n_in,
                              void* d_out, int out_size) {
    const int*   inds = (const int*)  d_in[0];
    const int*   lens = (const int*)  d_in[1];
    const float* emb  = (const float*)d_in[2];
    const float* w_ih = (const float*)d_in[3];
    const float* w_hh = (const float*)d_in[4];
    const float* b_ih = (const float*)d_in[5];
    const float* b_hh = (const float*)d_in[6];
    const float* sg_x = (const float*)d_in[7];
    const float* adj  = (const float*)d_in[8];
    const float* gw1  = (const float*)d_in[9];
    const float* gb1  = (const float*)d_in[10];
    const float* gw2  = (const float*)d_in[11];
    const float* gb2  = (const float*)d_in[12];
    float* out = (float*)d_out;

    const int WSMEM = 128 * 3 * 32 * 16;   // 196608 B dynamic smem
    cudaFuncSetAttribute(gru_persist_kernel,
                         cudaFuncAttributeMaxDynamicSharedMemorySize, WSMEM);

    cudaMemsetAsync(d_out, 0, (size_t)out_size * sizeof(float), 0);
    zero_h_kernel<<<(B3 * HDIM + 511) / 512, 512>>>();
    prep_kernel<<<1, 256>>>(lens);
    transpose_wih_kernel<<<512, 256>>>(w_ih);

    xi_gemm_kernel<<<dim3(G3 / XBN, (B3 * SLEN) / XBM), 256>>>(inds, emb, b_ih);

    msks_kernel<<<BS, TT>>>(out);
    pack_emb_kernel<<<dim3(SLEN, B3), 64>>>(inds, emb, out);

    gru_persist_kernel<<<dim3(NKG, NBG), 256, WSMEM>>>(w_hh, b_hh, out);

    // GCN
    gemm64_kernel<<<dim3((NHID + 63) / 64, (BN + 63) / 64), 256>>>(sg_x, gw1, g_t1, BN, NHID, NFEAT);
    adjmul_kernel<<<1350, 512>>>(adj, g_t1, gb1, g_h1, NHID, 1);
    gemm64_kernel<<<dim3((NOUT + 63) / 64, (BN + 63) / 64), 256>>>(g_h1, gw2, g_t2, BN, NOUT, NHID);
    adjmul_kernel<<<2304, 512>>>(adj, g_t2, gb2, out + OUT_SG, NOUT, 0);
}